// round 8
// baseline (speedup 1.0000x reference)
#include <cuda_runtime.h>
#include <cstdint>

// ---------------- problem constants ----------------
#define N_NODES 100000
#define N_EDGES 1600000
#define EP      (N_EDGES + N_NODES)   // edges + self loops = 1,700,000
#define EMB     64
#define HID     128
#define NEG     0.2f

// ---------------- device scratch (no allocs allowed) ----------------
__device__ float g_xl[N_NODES * EMB];
__device__ float g_xr[N_NODES * EMB];
__device__ float g_h [N_NODES * EMB];   // layer-1 output accumulator / layer-2 input
__device__ float g_h2[N_NODES * EMB];   // layer-2 output accumulator
__device__ float g_ex[EP];              // per-edge exp(score)
__device__ float g_denom[N_NODES];      // per-node softmax denominator
__device__ float g_easum;               // sum of edge_attr (for self-loop mean)

// ---------------- small helpers ----------------
__device__ __forceinline__ float leaky(float a) {
    // for 0 < NEG < 1: max(a, NEG*a) == leaky_relu(a)
    return fmaxf(a, NEG * a);
}

__device__ __forceinline__ void red_add_v2(float* p, float a, float b) {
    asm volatile("red.global.add.v2.f32 [%0], {%1, %2};"
                 :: "l"(p), "f"(a), "f"(b) : "memory");
}

// ---------------- kernels ----------------
__global__ void k_zero_easum() { g_easum = 0.0f; }

__global__ void k_sum_ea(const float* __restrict__ ea) {
    float s = 0.0f;
    for (int i = blockIdx.x * blockDim.x + threadIdx.x; i < N_EDGES;
         i += gridDim.x * blockDim.x)
        s += ea[i];
    #pragma unroll
    for (int o = 16; o; o >>= 1) s += __shfl_xor_sync(0xffffffffu, s, o);
    if ((threadIdx.x & 31) == 0) atomicAdd(&g_easum, s);
}

// Layer-1 feature transform: x[N,2] @ Wl/Wr[2,64] (+bias).
// Also zeroes the output accumulator and denom for this layer.
__global__ void k_transform1(const float* __restrict__ x,
                             const float* __restrict__ Wl, const float* __restrict__ bl,
                             const float* __restrict__ Wr, const float* __restrict__ br,
                             float* __restrict__ out_acc) {
    int idx = blockIdx.x * blockDim.x + threadIdx.x;
    if (idx >= N_NODES * EMB) return;
    int i = idx >> 6;
    int c = idx & 63;
    float x0 = x[2 * i + 0];
    float x1 = x[2 * i + 1];
    g_xl[idx] = fmaf(x0, Wl[c], fmaf(x1, Wl[EMB + c], bl[c]));
    g_xr[idx] = fmaf(x0, Wr[c], fmaf(x1, Wr[EMB + c], br[c]));
    out_acc[idx] = 0.0f;
    if (c == 0) g_denom[i] = 0.0f;
}

// Layer-2 feature transform: h[N,64] @ Wl/Wr[64,64] (+bias), weights staged in SMEM.
__global__ __launch_bounds__(256) void k_transform2(
        const float* __restrict__ h,
        const float* __restrict__ Wl, const float* __restrict__ bl,
        const float* __restrict__ Wr, const float* __restrict__ br,
        float* __restrict__ out_acc) {
    __shared__ float sWl[EMB * EMB];
    __shared__ float sWr[EMB * EMB];
    int tx = threadIdx.x & 63;        // output channel
    int ty = threadIdx.x >> 6;        // row within block (0..3)
    for (int j = threadIdx.x; j < EMB * EMB; j += 256) {
        sWl[j] = Wl[j];
        sWr[j] = Wr[j];
    }
    __syncthreads();

    int row = blockIdx.x * 4 + ty;
    if (row >= N_NODES) return;
    const float* hrow = h + row * EMB;
    float accl = bl[tx];
    float accr = br[tx];
    #pragma unroll
    for (int k = 0; k < EMB; k++) {
        float hk = hrow[k];                 // broadcast across 64 threads
        accl = fmaf(hk, sWl[k * EMB + tx], accl);
        accr = fmaf(hk, sWr[k * EMB + tx], accr);
    }
    int idx = row * EMB + tx;
    g_xl[idx] = accl;
    g_xr[idx] = accr;
    out_acc[idx] = 0.0f;
    if (tx == 0) g_denom[row] = 0.0f;
}

// Edge pass 1: score -> exp(score), accumulate softmax denominator.
// One warp per edge; each lane owns 2 channels (float2).
__global__ __launch_bounds__(256) void k_edge_score(
        const int* __restrict__ ei,          // [2, E] row-major
        const float* __restrict__ ea,        // [E]
        const float* __restrict__ We,        // [64]
        const float* __restrict__ att) {     // [64]
    int e = (blockIdx.x * blockDim.x + threadIdx.x) >> 5;
    if (e >= EP) return;
    int lane = threadIdx.x & 31;

    int s, d; float ev;
    if (e < N_EDGES) {
        s  = ei[e];
        d  = ei[N_EDGES + e];
        ev = ea[e];
    } else {
        s = d = e - N_EDGES;
        ev = g_easum * (1.0f / (float)N_EDGES);
    }

    float2 xlv = *reinterpret_cast<const float2*>(g_xl + s * EMB + 2 * lane);
    float2 xrv = *reinterpret_cast<const float2*>(g_xr + d * EMB + 2 * lane);
    float2 we  = *reinterpret_cast<const float2*>(We  + 2 * lane);
    float2 at  = *reinterpret_cast<const float2*>(att + 2 * lane);

    float a0 = leaky(fmaf(ev, we.x, xlv.x + xrv.x));
    float a1 = leaky(fmaf(ev, we.y, xlv.y + xrv.y));
    float p  = fmaf(at.x, a0, at.y * a1);

    #pragma unroll
    for (int o = 16; o; o >>= 1) p += __shfl_xor_sync(0xffffffffu, p, o);

    if (lane == 0) {
        float exv = __expf(p);
        g_ex[e] = exv;
        atomicAdd(&g_denom[d], exv);
    }
}

// Edge pass 2: out[dst] += (ex/denom[dst]) * xl[src], via vector RED.
__global__ __launch_bounds__(256) void k_edge_accum(
        const int* __restrict__ ei,
        float* __restrict__ out_acc) {
    int e = (blockIdx.x * blockDim.x + threadIdx.x) >> 5;
    if (e >= EP) return;
    int lane = threadIdx.x & 31;

    int s, d;
    if (e < N_EDGES) {
        s = ei[e];
        d = ei[N_EDGES + e];
    } else {
        s = d = e - N_EDGES;
    }

    float alpha = g_ex[e] / g_denom[d];
    float2 xlv = *reinterpret_cast<const float2*>(g_xl + s * EMB + 2 * lane);
    red_add_v2(out_acc + d * EMB + 2 * lane, alpha * xlv.x, alpha * xlv.y);
}

// h = relu(h + b)
__global__ void k_relu_bias(float* __restrict__ h, const float* __restrict__ b) {
    int idx = blockIdx.x * blockDim.x + threadIdx.x;
    if (idx >= N_NODES * EMB) return;
    h[idx] = fmaxf(h[idx] + b[idx & 63], 0.0f);
}

// Final head: out[1,128] = h2[target] @ Wf[64,128] + bf
__global__ void k_head(const float* __restrict__ h2,
                       const int* __restrict__ tgt,
                       const float* __restrict__ Wf,
                       const float* __restrict__ bf,
                       float* __restrict__ out) {
    int j = threadIdx.x;   // 0..127
    int t = tgt[0];
    const float* hrow = h2 + t * EMB;
    float acc = bf[j];
    #pragma unroll
    for (int c = 0; c < EMB; c++)
        acc = fmaf(hrow[c], Wf[c * HID + j], acc);
    out[j] = acc;
}

// ---------------- launch ----------------
extern "C" void kernel_launch(void* const* d_in, const int* in_sizes, int n_in,
                              void* d_out, int out_size) {
    const float* x    = (const float*)d_in[0];
    const int*   ei   = (const int*)  d_in[1];
    const float* ea   = (const float*)d_in[2];
    const int*   tgt  = (const int*)  d_in[3];
    const float* Wl1  = (const float*)d_in[4];
    const float* bl1  = (const float*)d_in[5];
    const float* Wr1  = (const float*)d_in[6];
    const float* br1  = (const float*)d_in[7];
    const float* We1  = (const float*)d_in[8];
    const float* att1 = (const float*)d_in[9];
    const float* b1   = (const float*)d_in[10];
    const float* Wl2  = (const float*)d_in[11];
    const float* bl2  = (const float*)d_in[12];
    const float* Wr2  = (const float*)d_in[13];
    const float* br2  = (const float*)d_in[14];
    const float* We2  = (const float*)d_in[15];
    const float* att2 = (const float*)d_in[16];
    const float* b2   = (const float*)d_in[17];
    const float* Wf   = (const float*)d_in[18];
    const float* bf   = (const float*)d_in[19];
    float* out = (float*)d_out;

    float* d_h;  cudaGetSymbolAddress((void**)&d_h,  g_h);
    float* d_h2; cudaGetSymbolAddress((void**)&d_h2, g_h2);

    const int NT = 256;
    int nodeElems  = N_NODES * EMB;
    int nodeBlocks = (nodeElems + NT - 1) / NT;
    long long edgeThreads = (long long)EP * 32;
    int edgeBlocks = (int)((edgeThreads + NT - 1) / NT);

    // edge_attr mean (for self-loop fill)
    k_zero_easum<<<1, 1>>>();
    k_sum_ea<<<512, NT>>>(ea);

    // ---- layer 1 ----
    k_transform1<<<nodeBlocks, NT>>>(x, Wl1, bl1, Wr1, br1, d_h);
    k_edge_score<<<edgeBlocks, NT>>>(ei, ea, We1, att1);
    k_edge_accum<<<edgeBlocks, NT>>>(ei, d_h);
    k_relu_bias<<<nodeBlocks, NT>>>(d_h, b1);

    // ---- layer 2 ----
    k_transform2<<<(N_NODES + 3) / 4, NT>>>(d_h, Wl2, bl2, Wr2, br2, d_h2);
    k_edge_score<<<edgeBlocks, NT>>>(ei, ea, We2, att2);
    k_edge_accum<<<edgeBlocks, NT>>>(ei, d_h2);
    k_relu_bias<<<nodeBlocks, NT>>>(d_h2, b2);

    // ---- head ----
    k_head<<<1, HID>>>(d_h2, tgt, Wf, bf, out);
}

// round 10
// speedup vs baseline: 2.2132x; 2.2132x over previous
#include <cuda_runtime.h>
#include <cstdint>

// ---------------- problem constants ----------------
#define N_NODES 100000
#define N_EDGES 1600000
#define EMB     64
#define HID     128
#define NEG     0.2f

// ---------------- device scratch (no allocs allowed) ----------------
__device__ float g_xl[N_NODES * EMB];
__device__ float g_xr[N_NODES * EMB];
__device__ float g_h [N_NODES * EMB];   // layer accumulator, becomes h in-place
__device__ float g_h2[N_NODES * EMB];
__device__ float g_denom[N_NODES];      // per-node softmax denominator (unshifted)
__device__ float g_easum;               // sum of edge_attr (self-loop mean)

// ---------------- helpers ----------------
__device__ __forceinline__ float leaky(float a) {
    return fmaxf(a, NEG * a);           // valid for 0 < NEG < 1
}

__device__ __forceinline__ void red_add_v4(float* p, float a, float b, float c, float d) {
    asm volatile("red.global.add.v4.f32 [%0], {%1, %2, %3, %4};"
                 :: "l"(p), "f"(a), "f"(b), "f"(c), "f"(d) : "memory");
}

// ---------------- kernels ----------------
__global__ void k_zero_easum() { g_easum = 0.0f; }

__global__ void k_sum_ea(const float* __restrict__ ea) {
    float s = 0.0f;
    for (int i = blockIdx.x * blockDim.x + threadIdx.x; i < N_EDGES;
         i += gridDim.x * blockDim.x)
        s += ea[i];
    #pragma unroll
    for (int o = 16; o; o >>= 1) s += __shfl_xor_sync(0xffffffffu, s, o);
    if ((threadIdx.x & 31) == 0) atomicAdd(&g_easum, s);
}

// Layer-1 transform: x[N,2] @ Wl/Wr[2,64] (+bias); zero acc + denom.
__global__ void k_transform1(const float* __restrict__ x,
                             const float* __restrict__ Wl, const float* __restrict__ bl,
                             const float* __restrict__ Wr, const float* __restrict__ br,
                             float* __restrict__ out_acc) {
    int idx = blockIdx.x * blockDim.x + threadIdx.x;
    if (idx >= N_NODES * EMB) return;
    int i = idx >> 6;
    int c = idx & 63;
    float x0 = x[2 * i + 0];
    float x1 = x[2 * i + 1];
    g_xl[idx] = fmaf(x0, Wl[c], fmaf(x1, Wl[EMB + c], bl[c]));
    g_xr[idx] = fmaf(x0, Wr[c], fmaf(x1, Wr[EMB + c], br[c]));
    out_acc[idx] = 0.0f;
    if (c == 0) g_denom[i] = 0.0f;
}

// Layer-2 transform: h[N,64] @ Wl/Wr[64,64] (+bias), SMEM-staged weights;
// zero acc + denom.
__global__ __launch_bounds__(256) void k_transform2(
        const float* __restrict__ h,
        const float* __restrict__ Wl, const float* __restrict__ bl,
        const float* __restrict__ Wr, const float* __restrict__ br,
        float* __restrict__ out_acc) {
    __shared__ float sWl[EMB * EMB];
    __shared__ float sWr[EMB * EMB];
    int tx = threadIdx.x & 63;
    int ty = threadIdx.x >> 6;
    for (int j = threadIdx.x; j < EMB * EMB; j += 256) {
        sWl[j] = Wl[j];
        sWr[j] = Wr[j];
    }
    __syncthreads();

    int row = blockIdx.x * 4 + ty;
    if (row >= N_NODES) return;
    const float* hrow = h + row * EMB;
    float accl = bl[tx];
    float accr = br[tx];
    #pragma unroll
    for (int k = 0; k < EMB; k++) {
        float hk = hrow[k];
        accl = fmaf(hk, sWl[k * EMB + tx], accl);
        accr = fmaf(hk, sWr[k * EMB + tx], accr);
    }
    int idx = row * EMB + tx;
    g_xl[idx] = accl;
    g_xr[idx] = accr;
    out_acc[idx] = 0.0f;
    if (tx == 0) g_denom[row] = 0.0f;
}

// FUSED edge pass: score -> ex; acc[dst] += ex * xl[src]; denom[dst] += ex.
// Half-warp (16 lanes) per edge, float4 per lane (64 channels).
// Real edges only — self-loops handled in k_finish.
__global__ __launch_bounds__(256) void k_edge_fused(
        const int*   __restrict__ ei,     // [2, E] row-major
        const float* __restrict__ ea,     // [E]
        const float* __restrict__ We,     // [64]
        const float* __restrict__ att,    // [64]
        float*       __restrict__ acc) {
    int lane = threadIdx.x & 31;
    int half = lane >> 4;                 // 0/1: which edge of the pair
    int l16  = lane & 15;                 // channel group within edge

    // hoisted per-lane constants
    float4 we = reinterpret_cast<const float4*>(We)[l16];
    float4 at = reinterpret_cast<const float4*>(att)[l16];

    int warpId = (blockIdx.x * blockDim.x + threadIdx.x) >> 5;
    int nwarps = (gridDim.x * blockDim.x) >> 5;

    // N_EDGES is even; e0 is always even, so both halves are always valid.
    #pragma unroll 2
    for (int e0 = warpId * 2; e0 < N_EDGES; e0 += nwarps * 2) {
        int e = e0 + half;
        int s = ei[e];
        int d = ei[N_EDGES + e];
        float ev = ea[e];

        float4 xl = reinterpret_cast<const float4*>(g_xl)[s * 16 + l16];
        float4 xr = reinterpret_cast<const float4*>(g_xr)[d * 16 + l16];

        float a0 = leaky(fmaf(ev, we.x, xl.x + xr.x));
        float a1 = leaky(fmaf(ev, we.y, xl.y + xr.y));
        float a2 = leaky(fmaf(ev, we.z, xl.z + xr.z));
        float a3 = leaky(fmaf(ev, we.w, xl.w + xr.w));
        float p = fmaf(at.x, a0, fmaf(at.y, a1, fmaf(at.z, a2, at.w * a3)));

        // butterfly within the 16-lane group
        #pragma unroll
        for (int o = 8; o; o >>= 1) p += __shfl_xor_sync(0xffffffffu, p, o);

        float exv = __expf(p);            // no max-shift needed: |score| small
        if (l16 == 0) atomicAdd(&g_denom[d], exv);
        red_add_v4(acc + d * EMB + l16 * 4,
                   exv * xl.x, exv * xl.y, exv * xl.z, exv * xl.w);
    }
}

// Node finish: add self-loop contribution locally (no gather, no atomics),
// normalize by denom, add bias, relu. In-place on the accumulator buffer.
__global__ __launch_bounds__(256) void k_finish(
        float* __restrict__ hbuf,         // in: acc, out: h
        const float* __restrict__ We,
        const float* __restrict__ att,
        const float* __restrict__ b) {
    int gtid = blockIdx.x * blockDim.x + threadIdx.x;
    int i   = gtid >> 4;
    int l16 = gtid & 15;
    if (i >= N_NODES) return;

    float evm = g_easum * (1.0f / (float)N_EDGES);
    float4 we = reinterpret_cast<const float4*>(We)[l16];
    float4 at = reinterpret_cast<const float4*>(att)[l16];
    float4 bb = reinterpret_cast<const float4*>(b)[l16];

    float4 xl = reinterpret_cast<const float4*>(g_xl)[i * 16 + l16];
    float4 xr = reinterpret_cast<const float4*>(g_xr)[i * 16 + l16];

    float a0 = leaky(fmaf(evm, we.x, xl.x + xr.x));
    float a1 = leaky(fmaf(evm, we.y, xl.y + xr.y));
    float a2 = leaky(fmaf(evm, we.z, xl.z + xr.z));
    float a3 = leaky(fmaf(evm, we.w, xl.w + xr.w));
    float p = fmaf(at.x, a0, fmaf(at.y, a1, fmaf(at.z, a2, at.w * a3)));
    #pragma unroll
    for (int o = 8; o; o >>= 1) p += __shfl_xor_sync(0xffffffffu, p, o);

    float exv = __expf(p);
    float inv = 1.0f / (g_denom[i] + exv);

    float4 acc = reinterpret_cast<const float4*>(hbuf)[i * 16 + l16];
    float4 out;
    out.x = fmaxf(fmaf(exv, xl.x, acc.x) * inv + bb.x, 0.0f);
    out.y = fmaxf(fmaf(exv, xl.y, acc.y) * inv + bb.y, 0.0f);
    out.z = fmaxf(fmaf(exv, xl.z, acc.z) * inv + bb.z, 0.0f);
    out.w = fmaxf(fmaf(exv, xl.w, acc.w) * inv + bb.w, 0.0f);
    reinterpret_cast<float4*>(hbuf)[i * 16 + l16] = out;
}

// Final head: out[1,128] = h2[target] @ Wf[64,128] + bf
__global__ void k_head(const float* __restrict__ h2,
                       const int* __restrict__ tgt,
                       const float* __restrict__ Wf,
                       const float* __restrict__ bf,
                       float* __restrict__ out) {
    int j = threadIdx.x;
    int t = tgt[0];
    const float* hrow = h2 + t * EMB;
    float acc = bf[j];
    #pragma unroll
    for (int c = 0; c < EMB; c++)
        acc = fmaf(hrow[c], Wf[c * HID + j], acc);
    out[j] = acc;
}

// ---------------- launch ----------------
extern "C" void kernel_launch(void* const* d_in, const int* in_sizes, int n_in,
                              void* d_out, int out_size) {
    const float* x    = (const float*)d_in[0];
    const int*   ei   = (const int*)  d_in[1];
    const float* ea   = (const float*)d_in[2];
    const int*   tgt  = (const int*)  d_in[3];
    const float* Wl1  = (const float*)d_in[4];
    const float* bl1  = (const float*)d_in[5];
    const float* Wr1  = (const float*)d_in[6];
    const float* br1  = (const float*)d_in[7];
    const float* We1  = (const float*)d_in[8];
    const float* att1 = (const float*)d_in[9];
    const float* b1   = (const float*)d_in[10];
    const float* Wl2  = (const float*)d_in[11];
    const float* bl2  = (const float*)d_in[12];
    const float* Wr2  = (const float*)d_in[13];
    const float* br2  = (const float*)d_in[14];
    const float* We2  = (const float*)d_in[15];
    const float* att2 = (const float*)d_in[16];
    const float* b2   = (const float*)d_in[17];
    const float* Wf   = (const float*)d_in[18];
    const float* bf   = (const float*)d_in[19];
    float* out = (float*)d_out;

    float* d_h;  cudaGetSymbolAddress((void**)&d_h,  g_h);
    float* d_h2; cudaGetSymbolAddress((void**)&d_h2, g_h2);

    const int NT = 256;
    int nodeElems  = N_NODES * EMB;
    int nodeBlocks = (nodeElems + NT - 1) / NT;
    int finishBlocks = (N_NODES * 16 + NT - 1) / NT;
    int edgeBlocks = 152 * 8;             // full-occupancy grid-stride

    // edge_attr mean (for self-loop fill)
    k_zero_easum<<<1, 1>>>();
    k_sum_ea<<<512, NT>>>(ea);

    // ---- layer 1 ----
    k_transform1<<<nodeBlocks, NT>>>(x, Wl1, bl1, Wr1, br1, d_h);
    k_edge_fused<<<edgeBlocks, NT>>>(ei, ea, We1, att1, d_h);
    k_finish<<<finishBlocks, NT>>>(d_h, We1, att1, b1);

    // ---- layer 2 ----
    k_transform2<<<(N_NODES + 3) / 4, NT>>>(d_h, Wl2, bl2, Wr2, br2, d_h2);
    k_edge_fused<<<edgeBlocks, NT>>>(ei, ea, We2, att2, d_h2);
    k_finish<<<finishBlocks, NT>>>(d_h2, We2, att2, b2);

    // ---- head ----
    k_head<<<1, HID>>>(d_h2, tgt, Wf, bf, out);
}